// round 10
// baseline (speedup 1.0000x reference)
#include <cuda_runtime.h>
#include <math.h>
#include <stdint.h>

#define M_TAGS   512
#define L_SEQ    4096
#define V_VOCAB  50000
#define VP1      50001
#define NCTA     16
#define THREADS  256
#define CPW      4          // columns per warp
#define FULLMASK 0xffffffffu

// ---- device scratch ----
__device__ float g_a0 [M_TAGS];
__device__ float g_ext[L_SEQ * M_TAGS];   // ext[t][j] = E[j, x[t]]
__device__ float g_phipath;

// ---- PTX helpers ----
__device__ __forceinline__ uint32_t smem_u32(const void* p) {
    uint32_t a;
    asm("{ .reg .u64 t; cvta.to.shared.u64 t, %1; cvt.u32.u64 %0, t; }" : "=r"(a) : "l"(p));
    return a;
}
__device__ __forceinline__ uint32_t mapa_u32(uint32_t addr, uint32_t rank) {
    uint32_t r;
    asm("mapa.shared::cluster.u32 %0, %1, %2;" : "=r"(r) : "r"(addr), "r"(rank));
    return r;
}
__device__ __forceinline__ uint32_t lds_vol_u32(uint32_t a) {
    uint32_t v;
    asm volatile("ld.volatile.shared.b32 %0, [%1];" : "=r"(v) : "r"(a));
    return v;
}
__device__ __forceinline__ float4 lds_vol_v4(uint32_t a) {
    float4 v;
    asm volatile("ld.volatile.shared.v4.f32 {%0,%1,%2,%3}, [%4];"
                 : "=f"(v.x), "=f"(v.y), "=f"(v.z), "=f"(v.w) : "r"(a));
    return v;
}
__device__ __forceinline__ void st_cluster_v4(uint32_t a, float4 v) {
    asm volatile("st.shared::cluster.v4.f32 [%0], {%1,%2,%3,%4};"
                 :: "r"(a), "f"(v.x), "f"(v.y), "f"(v.z), "f"(v.w));
}
__device__ __forceinline__ unsigned long long packdup(float x) {
    unsigned long long d; uint32_t u = __float_as_uint(x);
    asm("mov.b64 %0, {%1, %1};" : "=l"(d) : "r"(u)); return d;
}
__device__ __forceinline__ unsigned long long pack2(float x, float y) {
    unsigned long long d;
    asm("mov.b64 %0, {%1, %2};" : "=l"(d) : "r"(__float_as_uint(x)), "r"(__float_as_uint(y)));
    return d;
}
__device__ __forceinline__ void fma2(unsigned long long& d, unsigned long long a, unsigned long long b) {
    asm("fma.rn.f32x2 %0, %1, %2, %0;" : "+l"(d) : "l"(a), "l"(b));
}
__device__ __forceinline__ void add2(unsigned long long& d, unsigned long long a) {
    asm("add.rn.f32x2 %0, %0, %1;" : "+l"(d) : "l"(a));
}
__device__ __forceinline__ void unpack2(unsigned long long d, float& lo, float& hi) {
    uint32_t a, b;
    asm("mov.b64 {%0, %1}, %2;" : "=r"(a), "=r"(b) : "l"(d));
    lo = __uint_as_float(a); hi = __uint_as_float(b);
}
__device__ __forceinline__ void cluster_barrier() {
    asm volatile("barrier.cluster.arrive.aligned;" ::: "memory");
    asm volatile("barrier.cluster.wait.aligned;"   ::: "memory");
}

// =====================================================================
// Init: alpha0 -> g_a0, phi_path, ext gather
// =====================================================================
__global__ void crf_init_kernel(const float* __restrict__ T,
                                const float* __restrict__ E,
                                const float* __restrict__ Eprev,
                                const float* __restrict__ Enext,
                                const float* __restrict__ Cap,
                                const int*   __restrict__ x,
                                const int*   __restrict__ y,
                                const int*   __restrict__ upper)
{
    const int b   = blockIdx.x;
    const int tid = threadIdx.x;

    if (b == 0) {
        const int x0 = x[0], x1 = x[1], u0 = upper[0];
        for (int m = tid; m < M_TAGS; m += blockDim.x) {
            float phi = T[M_TAGS * M_TAGS + m]
                      + Eprev[m * VP1 + M_TAGS]
                      + Enext[m * VP1 + x1]
                      + Cap[m * 2 + u0]
                      + E[m * V_VOCAB + x0];
            g_a0[m] = expf(phi);
        }
    } else if (b == 1) {
        __shared__ float red[256];
        float acc = 0.f;
        for (int t = tid; t < L_SEQ; t += blockDim.x) {
            int yt = y[t];
            int yp = (t == 0)         ? M_TAGS : y[t - 1];
            int xp = (t == 0)         ? M_TAGS : x[t - 1];
            int xn = (t == L_SEQ - 1) ? M_TAGS : x[t + 1];
            acc += T[yp * M_TAGS + yt]
                 + Eprev[yt * VP1 + xp]
                 + Enext[yt * VP1 + xn]
                 + Cap[yt * 2 + upper[t]]
                 + E[yt * V_VOCAB + x[t]];
        }
        red[tid] = acc;
        __syncthreads();
        for (int s = 128; s > 0; s >>= 1) {
            if (tid < s) red[tid] += red[tid + s];
            __syncthreads();
        }
        if (tid == 0) g_phipath = red[0];
    } else {
        long long idx = (long long)(b - 2) * blockDim.x + tid;
        if (idx < (long long)L_SEQ * M_TAGS) {
            int t = (int)(idx >> 9);
            int j = (int)(idx & 511);
            g_ext[idx] = E[(long long)j * V_VOCAB + x[t]];
        }
    }
}

// =====================================================================
// Chain: one 16-CTA cluster, 256 thr/CTA, 4 cols/warp, 4-slot SMEM ring.
// Sign-parity readiness: a slot is reused every 4 steps; the sign of the
// stored values alternates (pw=(t>>2)&1), so stale data / init sentinels
// are automatically "not ready" and no retire stores are needed.
// Reductions: 4 interleaved 5-level shfl.xor butterflies (pipelined).
// =====================================================================
__global__ void __launch_bounds__(THREADS, 1) __cluster_dims__(NCTA, 1, 1)
crf_chain_kernel(const float* __restrict__ T, float* __restrict__ out)
{
    __shared__ float A[4][M_TAGS];     // 4-slot ring, 2KB per slot

    const int tid  = threadIdx.x;
    const int w    = tid >> 5;
    const int lane = tid & 31;
    const int rank = blockIdx.x;       // grid == one cluster
    const int c0   = rank * 32 + w * CPW;

    // ---- local init: alpha0 (positive = parity 0) in slot 0 ----
    A[0][tid]       = g_a0[tid];
    A[0][tid + 256] = g_a0[tid + 256];
    A[1][tid]       = -1.f;  A[1][tid + 256] = -1.f;
    A[2][tid]       = -1.f;  A[2][tid + 256] = -1.f;
    A[3][tid]       = -1.f;  A[3][tid + 256] = -1.f;
    __syncthreads();
    cluster_barrier();

    // ---- Tm slice into registers (lane-strided k: k = g*32 + lane) ----
    unsigned long long tm01[16], tm23[16];
    #pragma unroll
    for (int g = 0; g < 16; ++g) {
        int k = g * 32 + lane;
        float4 tv = *(const float4*)(T + (long long)k * M_TAGS + c0);
        tm01[g] = pack2(tv.x, tv.y);
        tm23[g] = pack2(tv.z, tv.w);
    }

    // ---- per-lane peer address: lane p (p<16) targets cluster rank p ----
    const uint32_t abase   = smem_u32(&A[0][0]);
    const uint32_t mypeer  = mapa_u32(abase, (uint32_t)(lane & 15));
    const uint32_t col_off = (uint32_t)(c0 << 2);

    float4 ext_next = *(const float4*)&g_ext[1 * M_TAGS + c0];  // broadcast
    float log_acc = 0.f;
    int   budget  = 1 << 25;           // fail loudly instead of hanging

    for (int t = 1; t < L_SEQ; ++t) {
        const uint32_t pr = (uint32_t)(((t - 1) >> 2) & 1);   // incoming parity
        const uint32_t ps = pr << 31;
        const uint32_t pw = (uint32_t)((t >> 2) & 1);         // outgoing parity

        // ---- detect slot (t-1)&3: sign(word) must equal pr ----
        const uint32_t rbase = abase + (((t - 1) & 3) << 11) + (lane << 4);
        for (;;) {
            uint32_t w0 = lds_vol_u32(rbase);
            uint32_t w1 = lds_vol_u32(rbase + 512);
            uint32_t w2 = lds_vol_u32(rbase + 1024);
            uint32_t w3 = lds_vol_u32(rbase + 1536);
            uint32_t yy = (w0 ^ ps) | (w1 ^ ps) | (w2 ^ ps) | (w3 ^ ps);
            if (__all_sync(FULLMASK, (int)yy >= 0)) break;
            if (--budget < 0) break;
        }
        // ---- fetch data once (signed values; groups are store-atomic) ----
        float4 v0 = lds_vol_v4(rbase);
        float4 v1 = lds_vol_v4(rbase + 512);
        float4 v2 = lds_vol_v4(rbase + 1024);
        float4 v3 = lds_vol_v4(rbase + 1536);

        // ---- 4 dot products via packed f32x2 FMA (signed inputs) ----
        float av[16] = { v0.x, v0.y, v0.z, v0.w,  v1.x, v1.y, v1.z, v1.w,
                         v2.x, v2.y, v2.z, v2.w,  v3.x, v3.y, v3.z, v3.w };
        unsigned long long acc01a = 0ull, acc01b = 0ull, acc23a = 0ull, acc23b = 0ull;
        #pragma unroll
        for (int g = 0; g < 16; g += 2) {
            unsigned long long aa = packdup(av[g]);
            unsigned long long bb = packdup(av[g + 1]);
            fma2(acc01a, aa, tm01[g]);
            fma2(acc23a, aa, tm23[g]);
            fma2(acc01b, bb, tm01[g + 1]);
            fma2(acc23b, bb, tm23[g + 1]);
        }
        add2(acc01a, acc01b);
        add2(acc23a, acc23b);
        float p0, p1, p2, p3;
        unpack2(acc01a, p0, p1);
        unpack2(acc23a, p2, p3);

        // ---- scale (sign algebra folded in) ----
        // non-renorm: o = (-1)^(pr^pw) * r * (1/128) * ext
        //   (t&3)==0 -> slot parity flips -> pr^pw = 1 -> negative
        // renorm:     o = (-1)^pw * (r/ss_signed) * (1/128) * ext
        float scale;
        if ((t & 255) == 0) {
            float ssl = ((av[0] + av[1]) + (av[2] + av[3]))
                      + ((av[4] + av[5]) + (av[6] + av[7]))
                      + ((av[8] + av[9]) + (av[10] + av[11]))
                      + ((av[12] + av[13]) + (av[14] + av[15]));
            #pragma unroll
            for (int off = 16; off; off >>= 1)
                ssl += __shfl_xor_sync(FULLMASK, ssl, off);
            scale = (pw ? -0.0078125f : 0.0078125f) / ssl;
            if (rank == 0 && tid == 0) log_acc += logf(fabsf(ssl));
        } else {
            scale = ((t & 3) == 0) ? -0.0078125f : 0.0078125f;
        }

        // ---- premultiply partials, then 4 interleaved shfl trees ----
        float r0 = p0 * (scale * ext_next.x);
        float r1 = p1 * (scale * ext_next.y);
        float r2 = p2 * (scale * ext_next.z);
        float r3 = p3 * (scale * ext_next.w);
        #pragma unroll
        for (int off = 16; off; off >>= 1) {
            r0 += __shfl_xor_sync(FULLMASK, r0, off);
            r1 += __shfl_xor_sync(FULLMASK, r1, off);
            r2 += __shfl_xor_sync(FULLMASK, r2, off);
            r3 += __shfl_xor_sync(FULLMASK, r3, off);
        }

        // ---- publish to all 16 CTAs in ONE SIMT store ----
        if (lane < 16)
            st_cluster_v4(mypeer + ((t & 3) << 11) + col_off,
                          make_float4(r0, r1, r2, r3));
        if (t + 1 < L_SEQ)
            ext_next = *(const float4*)&g_ext[(long long)(t + 1) * M_TAGS + c0];
    }

    // ---- finalize: rank 0, warp 0 ----
    if (rank == 0 && w == 0) {
        const uint32_t pr = (uint32_t)(((L_SEQ - 1) >> 2) & 1);
        const uint32_t ps = pr << 31;
        const uint32_t rbase = abase + (((L_SEQ - 1) & 3) << 11) + (lane << 4);
        for (;;) {
            uint32_t w0 = lds_vol_u32(rbase);
            uint32_t w1 = lds_vol_u32(rbase + 512);
            uint32_t w2 = lds_vol_u32(rbase + 1024);
            uint32_t w3 = lds_vol_u32(rbase + 1536);
            uint32_t yy = (w0 ^ ps) | (w1 ^ ps) | (w2 ^ ps) | (w3 ^ ps);
            if (__all_sync(FULLMASK, (int)yy >= 0)) break;
            if (--budget < 0) break;
        }
        float4 v0 = lds_vol_v4(rbase);
        float4 v1 = lds_vol_v4(rbase + 512);
        float4 v2 = lds_vol_v4(rbase + 1024);
        float4 v3 = lds_vol_v4(rbase + 1536);
        float ss = ((v0.x + v0.y) + (v0.z + v0.w))
                 + ((v1.x + v1.y) + (v1.z + v1.w))
                 + ((v2.x + v2.y) + (v2.z + v2.w))
                 + ((v3.x + v3.y) + (v3.z + v3.w));
        #pragma unroll
        for (int off = 16; off; off >>= 1)
            ss += __shfl_xor_sync(FULLMASK, ss, off);
        if (lane == 0) {
            // ln(128) = 7*ln(2) = 4.852030263919617
            double logz = (double)logf(fabsf(ss))
                        + 4095.0 * 4.852030263919617
                        + (double)log_acc;
            out[0] = (float)(logz - (double)g_phipath);
        }
    }

    // ---- exit fence: no CTA leaves while peers may still write here ----
    cluster_barrier();
}

// =====================================================================
extern "C" void kernel_launch(void* const* d_in, const int* in_sizes, int n_in,
                              void* d_out, int out_size)
{
    const float* T     = (const float*)d_in[0];
    const float* E     = (const float*)d_in[1];
    const float* Eprev = (const float*)d_in[2];
    const float* Enext = (const float*)d_in[3];
    const float* Cap   = (const float*)d_in[4];
    const int*   x     = (const int*)d_in[5];
    const int*   y     = (const int*)d_in[6];
    const int*   upper = (const int*)d_in[7];
    float*       out   = (float*)d_out;
    (void)in_sizes; (void)n_in; (void)out_size;

    // allow the 16-CTA (nonportable) cluster
    cudaFuncSetAttribute(crf_chain_kernel,
                         cudaFuncAttributeNonPortableClusterSizeAllowed, 1);

    const int ext_blocks = (L_SEQ * M_TAGS + 255) / 256;   // 8192
    crf_init_kernel<<<2 + ext_blocks, 256>>>(T, E, Eprev, Enext, Cap, x, y, upper);
    crf_chain_kernel<<<NCTA, THREADS>>>(T, out);
}